// round 13
// baseline (speedup 1.0000x reference)
#include <cuda_runtime.h>
#include <cuda_fp16.h>
#include <math.h>
#include <stdint.h>

#define TT 8192
#define DD 4096
#define RR 512
#define NH 32
#define HD 128

// Scratch (static __device__ arrays — allocation-free per harness rules)
__device__ float g_q [(size_t)TT * DD];           // reused as half q
__device__ float g_k [(size_t)RR * DD];           // reused as half k
__device__ float g_v [(size_t)RR * DD];           // reused as half v
__device__ __half h_a [(size_t)TT * DD];          // xq (half), later y (half)
__device__ __half h_b [(size_t)TT * DD];          // o (half), later gelu out (half)
__device__ __half h_xc[(size_t)RR * DD];
__device__ __half h_w [6][(size_t)DD * DD];       // transposed half weights [N][K]

__device__ __forceinline__ float gelu_f(float v) {
    return 0.5f * v * (1.0f + erff(v * 0.70710678118654752f));
}

__device__ __forceinline__ void cp16(uint32_t smem, const void* g) {
    asm volatile("cp.async.cg.shared.global [%0], [%1], 16;\n" :: "r"(smem), "l"(g));
}
__device__ __forceinline__ void cp_commit() {
    asm volatile("cp.async.commit_group;\n" ::: "memory");
}
template<int N>
__device__ __forceinline__ void cp_wait() {
    asm volatile("cp.async.wait_group %0;\n" :: "n"(N) : "memory");
}

__device__ __forceinline__ void mma_f16(
    float* c, const uint32_t* a, const uint32_t* b)
{
    asm volatile(
        "mma.sync.aligned.m16n8k16.row.col.f32.f16.f16.f32 "
        "{%0,%1,%2,%3}, {%4,%5,%6,%7}, {%8,%9}, {%0,%1,%2,%3};\n"
        : "+f"(c[0]), "+f"(c[1]), "+f"(c[2]), "+f"(c[3])
        : "r"(a[0]), "r"(a[1]), "r"(a[2]), "r"(a[3]),
          "r"(b[0]), "r"(b[1]));
}

#define LDSM4(r0, r1, r2, r3, addr)                                             \
    asm volatile("ldmatrix.sync.aligned.m8n8.x4.shared.b16 {%0,%1,%2,%3}, [%4];"\
        : "=r"(r0), "=r"(r1), "=r"(r2), "=r"(r3) : "r"(addr))

// clamp before half conversion: no-op for correct magnitudes.
__device__ __forceinline__ float clampf(float v) {
    return fminf(fmaxf(v, -1.0e4f), 1.0e4f);
}

// ---------------------------------------------------------------------------
// Weight transpose-convert: W fp32 [K][N] -> Wh half [N][K]
// ---------------------------------------------------------------------------
__global__ __launch_bounds__(256) void w2h_t(
    const float* __restrict__ W, __half* __restrict__ Wh)
{
    __shared__ float tile[32][33];
    int tx = threadIdx.x, ty = threadIdx.y;        // 32 x 8
    int n0 = blockIdx.x * 32, k0 = blockIdx.y * 32;
    #pragma unroll
    for (int i = 0; i < 4; i++)
        tile[ty + 8 * i][tx] = W[(size_t)(k0 + ty + 8 * i) * DD + n0 + tx];
    __syncthreads();
    #pragma unroll
    for (int i = 0; i < 4; i++)
        Wh[(size_t)(n0 + ty + 8 * i) * DD + k0 + tx] =
            __float2half_rn(tile[tx][ty + 8 * i]);
}

// ---------------------------------------------------------------------------
// LayerNorm: one block per row, D = 4096. FOUT fp32 out, HOUT half out.
// ---------------------------------------------------------------------------
template<bool FOUT, bool HOUT>
__global__ __launch_bounds__(256) void ln_kernel(
    const float* __restrict__ x, const float* __restrict__ w,
    const float* __restrict__ b, float* __restrict__ y, __half* __restrict__ yh)
{
    __shared__ float red[64];
    int row = blockIdx.x;
    int tid = threadIdx.x;
    const float4* xr = (const float4*)(x + (size_t)row * DD);

    float sum = 0.f, ssq = 0.f;
    #pragma unroll 4
    for (int i = tid; i < DD / 4; i += 256) {
        float4 v = xr[i];
        sum += v.x + v.y + v.z + v.w;
        ssq += v.x * v.x + v.y * v.y + v.z * v.z + v.w * v.w;
    }
    #pragma unroll
    for (int o = 16; o; o >>= 1) {
        sum += __shfl_xor_sync(0xffffffffu, sum, o);
        ssq += __shfl_xor_sync(0xffffffffu, ssq, o);
    }
    if ((tid & 31) == 0) { red[tid >> 5] = sum; red[32 + (tid >> 5)] = ssq; }
    __syncthreads();
    if (tid < 32) {
        float s = (tid < 8) ? red[tid] : 0.f;
        float q = (tid < 8) ? red[32 + tid] : 0.f;
        #pragma unroll
        for (int o = 4; o; o >>= 1) {
            s += __shfl_xor_sync(0xffffffffu, s, o);
            q += __shfl_xor_sync(0xffffffffu, q, o);
        }
        if (tid == 0) { red[0] = s; red[1] = q; }
    }
    __syncthreads();
    float mean = red[0] * (1.0f / DD);
    float var  = red[1] * (1.0f / DD) - mean * mean;
    float inv  = rsqrtf(var + 1e-5f);

    const float4* wr = (const float4*)w;
    const float4* br = (const float4*)b;
    for (int i = tid; i < DD / 4; i += 256) {
        float4 v = xr[i], wv = wr[i], bv = br[i], r;
        r.x = (v.x - mean) * inv * wv.x + bv.x;
        r.y = (v.y - mean) * inv * wv.y + bv.y;
        r.z = (v.z - mean) * inv * wv.z + bv.z;
        r.w = (v.w - mean) * inv * wv.w + bv.w;
        if (FOUT) ((float4*)(y + (size_t)row * DD))[i] = r;
        if (HOUT) {
            __half2 h0 = __floats2half2_rn(r.x, r.y);
            __half2 h1 = __floats2half2_rn(r.z, r.w);
            uint2 u;
            u.x = *(uint32_t*)&h0; u.y = *(uint32_t*)&h1;
            ((uint2*)(yh + (size_t)row * DD))[i] = u;
        }
    }
}

// ---------------------------------------------------------------------------
// fp16 tensor-core GEMM with ldmatrix fragment loads (round-11 proven).
// HR1: R1 residual is half (reinterpreted from the R1 pointer).
// ---------------------------------------------------------------------------
#define KTILE      32
#define RPITCH     40                          // halfs per smem row
#define MAT_HALFS  (128 * RPITCH)              // 5120
#define STAGEB     (2 * MAT_HALFS * 2)         // 20480 bytes
#define GSMEM      (4 * STAGEB)                // 81920 bytes

extern __shared__ float dsm[];

template<int NRES, bool GELU, bool HOUT, bool HR1>
__device__ void gemm_core(
    const __half* __restrict__ A, const __half* __restrict__ B,
    float* __restrict__ C, __half* __restrict__ Ch,
    const float* __restrict__ R1, const float* __restrict__ R2,
    int N, int K, int bm, int bn)
{
    int tid  = threadIdx.x;
    int warp = tid >> 5, lane = tid & 31;
    int wm = (warp & 1) * 64;
    int wn = (warp >> 1) * 32;
    int rr = lane >> 2, ck = lane & 3;

    uint32_t smb = (uint32_t)__cvta_generic_to_shared(dsm);

    int l15   = lane & 15;
    int acol  = lane & 16;
    int l7    = lane & 7;
    int brow8 = (lane & 16) ? 8 : 0;
    int bcol  = (lane & 8) ? 16 : 0;

    float acc[4][4][4];
    #pragma unroll
    for (int mi = 0; mi < 4; mi++)
        #pragma unroll
        for (int ni = 0; ni < 4; ni++)
            #pragma unroll
            for (int e = 0; e < 4; e++) acc[mi][ni][e] = 0.f;

    int nk = K / KTILE;

    #define ISSUE(ktile, slot)                                                   \
    do {                                                                         \
        int _k0 = (ktile) * KTILE;                                               \
        uint32_t _sb = smb + (uint32_t)(slot) * STAGEB;                          \
        _Pragma("unroll")                                                        \
        for (int _i = 0; _i < 2; _i++) {                                         \
            int _c = tid + _i * 256;                                             \
            int _r = _c >> 2, _q = _c & 3;                                       \
            cp16(_sb + (uint32_t)(_r * 80 + _q * 16),                            \
                 A + (size_t)(bm + _r) * K + _k0 + _q * 8);                      \
        }                                                                        \
        _Pragma("unroll")                                                        \
        for (int _i = 0; _i < 2; _i++) {                                         \
            int _c = tid + _i * 256;                                             \
            int _n = _c >> 2, _q = _c & 3;                                       \
            cp16(_sb + (uint32_t)(MAT_HALFS * 2 + _n * 80 + _q * 16),            \
                 B + (size_t)(bn + _n) * K + _k0 + _q * 8);                      \
        }                                                                        \
        cp_commit();                                                             \
    } while (0)

    ISSUE(0, 0);
    ISSUE(1, 1);
    ISSUE(2, 2);

    for (int kt = 0; kt < nk; kt++) {
        cp_wait<2>();
        __syncthreads();

        int nxt = kt + 3;
        if (nxt < nk) { ISSUE(nxt, nxt & 3); }
        else          { cp_commit(); }

        uint32_t abase = smb + (uint32_t)(kt & 3) * STAGEB;
        uint32_t bbase = abase + (uint32_t)(MAT_HALFS * 2);

        #pragma unroll
        for (int ks = 0; ks < 2; ks++) {
            uint32_t af[4][4], bf[4][2];
            #pragma unroll
            for (int mi = 0; mi < 4; mi++) {
                uint32_t addr = abase +
                    (uint32_t)((wm + mi * 16 + l15) * 80 + ks * 32 + acol);
                LDSM4(af[mi][0], af[mi][1], af[mi][2], af[mi][3], addr);
            }
            #pragma unroll
            for (int p = 0; p < 2; p++) {
                uint32_t addr = bbase +
                    (uint32_t)((wn + p * 16 + l7 + brow8) * 80 + ks * 32 + bcol);
                LDSM4(bf[2 * p][0], bf[2 * p][1],
                      bf[2 * p + 1][0], bf[2 * p + 1][1], addr);
            }
            #pragma unroll
            for (int mi = 0; mi < 4; mi++)
                #pragma unroll
                for (int ni = 0; ni < 4; ni++)
                    mma_f16(acc[mi][ni], af[mi], bf[ni]);
        }
    }
    #undef ISSUE

    #pragma unroll
    for (int mi = 0; mi < 4; mi++) {
        #pragma unroll
        for (int hf = 0; hf < 2; hf++) {
            int r = bm + wm + mi * 16 + rr + hf * 8;
            #pragma unroll
            for (int ni = 0; ni < 4; ni++) {
                int c = bn + wn + ni * 8 + 2 * ck;
                float v0 = acc[mi][ni][hf * 2 + 0];
                float v1 = acc[mi][ni][hf * 2 + 1];
                if (GELU) { v0 = gelu_f(v0); v1 = gelu_f(v1); }
                size_t off = (size_t)r * N + c;
                if (HOUT) {
                    __half2 hh = __floats2half2_rn(v0, v1);
                    *(__half2*)&Ch[off] = hh;
                } else {
                    if (NRES >= 1) {
                        if (HR1) {
                            __half2 r1 = *(const __half2*)&((const __half*)R1)[off];
                            v0 += __half2float(r1.x); v1 += __half2float(r1.y);
                        } else {
                            float2 r1 = *(const float2*)&R1[off];
                            v0 += r1.x; v1 += r1.y;
                        }
                    }
                    if (NRES >= 2) {
                        float2 r2 = *(const float2*)&R2[off];
                        v0 += r2.x; v1 += r2.y;
                    }
                    float2 o = make_float2(v0, v1);
                    *(float2*)&C[off] = o;
                }
            }
        }
    }
}

template<int NRES, bool GELU, bool HOUT, bool HR1>
__global__ __launch_bounds__(256, 2) void hgemm_k(
    const __half* __restrict__ A, const __half* __restrict__ B,
    float* __restrict__ C, __half* __restrict__ Ch,
    const float* __restrict__ R1, const float* __restrict__ R2,
    int N, int K)
{
    gemm_core<NRES, GELU, HOUT, HR1>(A, B, C, Ch, R1, R2, N, K,
                                     blockIdx.y * 128, blockIdx.x * 128);
}

// Batched q/k/v projection -> half outputs. grid (32, 72).
__global__ __launch_bounds__(256, 2) void qkv_k(
    const __half* __restrict__ xqh, const __half* __restrict__ xch,
    const __half* __restrict__ Wqh, const __half* __restrict__ Wkh,
    const __half* __restrict__ Wvh,
    __half* __restrict__ q, __half* __restrict__ k, __half* __restrict__ v)
{
    int by = blockIdx.y, bn = blockIdx.x * 128;
    if (by < 64)
        gemm_core<0, false, true, false>(xqh, Wqh, nullptr, q, nullptr, nullptr, DD, DD, by * 128, bn);
    else if (by < 68)
        gemm_core<0, false, true, false>(xch, Wkh, nullptr, k, nullptr, nullptr, DD, DD, (by - 64) * 128, bn);
    else
        gemm_core<0, false, true, false>(xch, Wvh, nullptr, v, nullptr, nullptr, DD, DD, (by - 68) * 128, bn);
}

// ---------------------------------------------------------------------------
// Fused cross-attention, full fp16 mma (m16n8k16), 2 CTAs/SM (round-12 proven).
// ---------------------------------------------------------------------------
#define QP  136                               // q/k/v smem pitch (halfs)
#define PP  520                               // score pitch (halfs)
#define AQ_OFF  0
#define AKV_OFF (64 * QP)                     // 8704 halfs
#define AP_OFF  (2 * 64 * QP)                 // 17408 halfs
#define ATTN_SMEM ((2 * 64 * QP + 64 * PP) * 2)   // 101376 bytes

__global__ __launch_bounds__(256, 2) void attn_kernel(
    const __half* __restrict__ q, const __half* __restrict__ k,
    const __half* __restrict__ v, __half* __restrict__ o)
{
    extern __shared__ float sm_f[];
    __half* hsm  = (__half*)sm_f;
    __half* q_s  = hsm + AQ_OFF;
    __half* kv_s = hsm + AKV_OFF;
    __half* p_s  = hsm + AP_OFF;

    int tid  = threadIdx.x;
    int warp = tid >> 5, lane = tid & 31;
    int rr = lane >> 2, ck = lane & 3;
    int h   = blockIdx.y;
    int t0  = blockIdx.x * 64;
    size_t hoff = (size_t)h * HD;

    #pragma unroll
    for (int it = 0; it < 4; it++) {
        int idx = tid + it * 256;
        int r = idx >> 4, c = idx & 15;
        *(uint4*)&q_s[r * QP + c * 8] =
            *(const uint4*)&q[(size_t)(t0 + r) * DD + hoff + c * 8];
    }

    const float scale = 0.08838834764831845f;
    int wmA = (warp & 1) * 32;
    int wnA = (warp >> 1) * 16;

    // ---- Phase A: S = Q @ K^T ----
    for (int rc = 0; rc < RR / 64; rc++) {
        __syncthreads();
        #pragma unroll
        for (int it = 0; it < 4; it++) {
            int idx = tid + it * 256;
            int r = idx >> 4, c = idx & 15;
            *(uint4*)&kv_s[r * QP + c * 8] =
                *(const uint4*)&k[(size_t)(rc * 64 + r) * DD + hoff + c * 8];
        }
        __syncthreads();

        float acc[2][2][4];
        #pragma unroll
        for (int mi = 0; mi < 2; mi++)
            #pragma unroll
            for (int ni = 0; ni < 2; ni++)
                #pragma unroll
                for (int e = 0; e < 4; e++) acc[mi][ni][e] = 0.f;

        #pragma unroll
        for (int ks = 0; ks < 8; ks++) {
            int kk = ks * 16 + 2 * ck;
            uint32_t af[2][4], bf[2][2];
            #pragma unroll
            for (int mi = 0; mi < 2; mi++) {
                int m0 = wmA + mi * 16 + rr;
                af[mi][0] = *(const uint32_t*)&q_s[m0 * QP + kk];
                af[mi][1] = *(const uint32_t*)&q_s[(m0 + 8) * QP + kk];
                af[mi][2] = *(const uint32_t*)&q_s[m0 * QP + kk + 8];
                af[mi][3] = *(const uint32_t*)&q_s[(m0 + 8) * QP + kk + 8];
            }
            #pragma unroll
            for (int ni = 0; ni < 2; ni++) {
                int n0 = wnA + ni * 8 + rr;
                bf[ni][0] = *(const uint32_t*)&kv_s[n0 * QP + kk];
                bf[ni][1] = *(const uint32_t*)&kv_s[n0 * QP + kk + 8];
            }
            #pragma unroll
            for (int mi = 0; mi < 2; mi++)
                #pragma unroll
                for (int ni = 0; ni < 2; ni++)
                    mma_f16(acc[mi][ni], af[mi], bf[ni]);
        }

        #pragma unroll
        for (int mi = 0; mi < 2; mi++)
            #pragma unroll
            for (int hf = 0; hf < 2; hf++) {
                int r = wmA + mi * 16 + rr + hf * 8;
                #pragma unroll
                for (int ni = 0; ni < 2; ni++) {
                    int c = rc * 64 + wnA + ni * 8 + 2 * ck;
                    __half2 hh = __floats2half2_rn(
                        clampf(acc[mi][ni][hf * 2 + 0] * scale),
                        clampf(acc[mi][ni][hf * 2 + 1] * scale));
                    *(__half2*)&p_s[r * PP + c] = hh;
                }
            }
    }
    __syncthreads();

    // ---- softmax over R=512 (fp32 math, half storage) ----
    {
        int row = tid >> 2, l4 = tid & 3;
        __half* pr = p_s + row * PP;
        float mx = -1e30f;
        #pragma unroll 4
        for (int i = l4; i < RR; i += 4) mx = fmaxf(mx, __half2float(pr[i]));
        mx = fmaxf(mx, __shfl_xor_sync(0xffffffffu, mx, 1));
        mx = fmaxf(mx, __shfl_xor_sync(0xffffffffu, mx, 2));
        float sme = 0.f;
        #pragma unroll 4
        for (int i = l4; i < RR; i += 4) {
            float e = expf(__half2float(pr[i]) - mx);
            pr[i] = __float2half_rn(e); sme += e;
        }
        sme += __shfl_xor_sync(0xffffffffu, sme, 1);
        sme += __shfl_xor_sync(0xffffffffu, sme, 2);
        float inv = 1.0f / sme;
        #pragma unroll 4
        for (int i = l4; i < RR; i += 4)
            pr[i] = __float2half_rn(__half2float(pr[i]) * inv);
    }

    // ---- Phase B: O = P @ V ----
    int wnB = (warp >> 1) * 32;
    float acc2[2][4][4];
    #pragma unroll
    for (int mi = 0; mi < 2; mi++)
        #pragma unroll
        for (int ni = 0; ni < 4; ni++)
            #pragma unroll
            for (int e = 0; e < 4; e++) acc2[mi][ni][e] = 0.f;

    for (int rc = 0; rc < RR / 64; rc++) {
        __syncthreads();
        #pragma unroll
        for (int it = 0; it < 4; it++) {
            int idx = tid + it * 256;
            int r = idx >> 4, c = idx & 15;
            *(uint4*)&kv_s[r * QP + c * 8] =
                *(const uint4*)&v[(size_t)(rc * 64 + r) * DD + hoff + c * 8];
        }
        __syncthreads();

        #pragma unroll
        for (int ks = 0; ks < 4; ks++) {
            int kg = rc * 64 + ks * 16 + 2 * ck;
            int kb = ks * 16 + 2 * ck;
            uint32_t af[2][4], bf[4][2];
            #pragma unroll
            for (int mi = 0; mi < 2; mi++) {
                int m0 = wmA + mi * 16 + rr;
                af[mi][0] = *(const uint32_t*)&p_s[m0 * PP + kg];
                af[mi][1] = *(const uint32_t*)&p_s[(m0 + 8) * PP + kg];
                af[mi][2] = *(const uint32_t*)&p_s[m0 * PP + kg + 8];
                af[mi][3] = *(const uint32_t*)&p_s[(m0 + 8) * PP + kg + 8];
            }
            #pragma unroll
            for (int ni = 0; ni < 4; ni++) {
                int n0 = wnB + ni * 8 + rr;
                __half2 b0 = __halves2half2(kv_s[kb * QP + n0],
                                            kv_s[(kb + 1) * QP + n0]);
                __half2 b1 = __halves2half2(kv_s[(kb + 8) * QP + n0],
                                            kv_s[(kb + 9) * QP + n0]);
                bf[ni][0] = *(uint32_t*)&b0;
                bf[ni][1] = *(uint32_t*)&b1;
            }
            #pragma unroll
            for (int mi = 0; mi < 2; mi++)
                #pragma unroll
                for (int ni = 0; ni < 4; ni++)
                    mma_f16(acc2[mi][ni], af[mi], bf[ni]);
        }
    }

    #pragma unroll
    for (int mi = 0; mi < 2; mi++)
        #pragma unroll
        for (int hf = 0; hf < 2; hf++) {
            int r = t0 + wmA + mi * 16 + rr + hf * 8;
            #pragma unroll
            for (int ni = 0; ni < 4; ni++) {
                int c = wnB + ni * 8 + 2 * ck;
                __half2 hh = __floats2half2_rn(clampf(acc2[mi][ni][hf * 2 + 0]),
                                               clampf(acc2[mi][ni][hf * 2 + 1]));
                *(__half2*)&o[(size_t)r * DD + hoff + c] = hh;
            }
        }
}

// ---------------------------------------------------------------------------
extern "C" void kernel_launch(void* const* d_in, const int* in_sizes, int n_in,
                              void* d_out, int out_size)
{
    const float* x       = (const float*)d_in[0];
    /* d_in[1] = seqlens (int32) — blocks identical => dense attention, unused */
    const float* latents = (const float*)d_in[2];
    const float* ln_q_w  = (const float*)d_in[3];
    const float* ln_q_b  = (const float*)d_in[4];
    const float* ln_c_w  = (const float*)d_in[5];
    const float* ln_c_b  = (const float*)d_in[6];
    const float* Wq      = (const float*)d_in[7];
    const float* Wk      = (const float*)d_in[8];
    const float* Wv      = (const float*)d_in[9];
    const float* Wo      = (const float*)d_in[10];
    const float* ln_m_w  = (const float*)d_in[11];
    const float* ln_m_b  = (const float*)d_in[12];
    const float* W1      = (const float*)d_in[13];
    const float* W2      = (const float*)d_in[14];
    float* out = (float*)d_out;

    __half *qh, *kh, *vh, *ha, *hb, *hxc, *hw;
    cudaGetSymbolAddress((void**)&qh, g_q);
    cudaGetSymbolAddress((void**)&kh, g_k);
    cudaGetSymbolAddress((void**)&vh, g_v);
    cudaGetSymbolAddress((void**)&ha, h_a);
    cudaGetSymbolAddress((void**)&hb, h_b);
    cudaGetSymbolAddress((void**)&hxc, h_xc);
    cudaGetSymbolAddress((void**)&hw, h_w);
    __half* hw0 = hw;
    __half* hw1 = hw + 1 * (size_t)DD * DD;
    __half* hw2 = hw + 2 * (size_t)DD * DD;
    __half* hw3 = hw + 3 * (size_t)DD * DD;
    __half* hw4 = hw + 4 * (size_t)DD * DD;
    __half* hw5 = hw + 5 * (size_t)DD * DD;

    cudaFuncSetAttribute(qkv_k, cudaFuncAttributeMaxDynamicSharedMemorySize, GSMEM);
    cudaFuncSetAttribute(hgemm_k<1, false, false, false>, cudaFuncAttributeMaxDynamicSharedMemorySize, GSMEM);
    cudaFuncSetAttribute(hgemm_k<0, true,  true,  false>, cudaFuncAttributeMaxDynamicSharedMemorySize, GSMEM);
    cudaFuncSetAttribute(hgemm_k<2, false, false, true>,  cudaFuncAttributeMaxDynamicSharedMemorySize, GSMEM);
    cudaFuncSetAttribute(attn_kernel, cudaFuncAttributeMaxDynamicSharedMemorySize, ATTN_SMEM);

    // Stream/event handles created once (before any capture call) — no device
    // allocation happens inside the captured region.
    static cudaStream_t s2 = 0;
    static cudaEvent_t evFork = 0, evJoin = 0;
    if (!s2) {
        cudaStreamCreateWithFlags(&s2, cudaStreamNonBlocking);
        cudaEventCreateWithFlags(&evFork, cudaEventDisableTiming);
        cudaEventCreateWithFlags(&evJoin, cudaEventDisableTiming);
    }

    dim3 tb(32, 8);
    dim3 tg(DD / 32, DD / 32);

    // Fork: weight converts on s2 run concurrently with the LayerNorms.
    cudaEventRecord(evFork, 0);
    cudaStreamWaitEvent(s2, evFork, 0);
    w2h_t<<<tg, tb, 0, s2>>>(Wq, hw0);
    w2h_t<<<tg, tb, 0, s2>>>(Wk, hw1);
    w2h_t<<<tg, tb, 0, s2>>>(Wv, hw2);
    w2h_t<<<tg, tb, 0, s2>>>(Wo, hw3);
    w2h_t<<<tg, tb, 0, s2>>>(W1, hw4);
    w2h_t<<<tg, tb, 0, s2>>>(W2, hw5);
    cudaEventRecord(evJoin, s2);

    // 1) LayerNorms -> half activations (default stream, concurrent with w2h)
    ln_kernel<false, true><<<TT, 256>>>(x, ln_q_w, ln_q_b, nullptr, ha);
    ln_kernel<false, true><<<RR, 256>>>(latents, ln_c_w, ln_c_b, nullptr, hxc);

    // Join before the first consumer of the converted weights.
    cudaStreamWaitEvent(0, evJoin, 0);

    // 2) Batched q/k/v projections (fp16 mma + ldmatrix) -> half
    qkv_k<<<dim3(DD / 128, 72), 256, GSMEM>>>(ha, hxc, hw0, hw1, hw2, qh, kh, vh);

    // 3) Fused attention (full fp16) -> half o
    attn_kernel<<<dim3(TT / 64, NH), 256, ATTN_SMEM>>>(qh, kh, vh, hb);

    // 4) hiddens = o @ Wo + x   (into d_out, fp32)
    hgemm_k<1, false, false, false><<<dim3(DD / 128, TT / 128), 256, GSMEM>>>(
        hb, hw3, out, nullptr, x, nullptr, DD, DD);

    // 5) y = LN(hiddens) -> half only (residual read back as half in step 7)
    ln_kernel<false, true><<<TT, 256>>>(out, ln_m_w, ln_m_b, nullptr, ha);

    // 6) g = gelu(y @ W1) -> half
    hgemm_k<0, true, true, false><<<dim3(DD / 128, TT / 128), 256, GSMEM>>>(
        ha, hw4, nullptr, hb, nullptr, nullptr, DD, DD);

    // 7) out = g @ W2 + y(half) + hiddens
    hgemm_k<2, false, false, true><<<dim3(DD / 128, TT / 128), 256, GSMEM>>>(
        hb, hw5, out, nullptr, (const float*)ha, out, DD, DD);
}